// round 8
// baseline (speedup 1.0000x reference)
#include <cuda_runtime.h>

#define BATCH 32
#define HH 1024
#define WW 1024
#define WPR 32
#define WORDS_PER_IMG (HH * WPR)
#define NWORDS (BATCH * WORDS_PER_IMG)   // 1048576
#define NCELLS (BATCH * HH * WW)         // 33554432

#define TH 64
#define SH (TH + 16)
#define SW 34
#define NSIM  (BATCH * (HH / TH))        // 512 sim blocks
#define NCOPY (NCELLS / 2048)            // 16384 copy blocks (2048 cells each)
#define NRED  1024                       // reduce blocks

__device__ unsigned g_A[NWORDS];
__device__ unsigned g_B[NWORDS];
__device__ unsigned g_T[NWORDS];
__device__ unsigned long long g_live;
__device__ unsigned long long g_mism;
__device__ unsigned g_done;

// ---------------------------------------------------------------------------
// K1: pack initial floats -> bits. Thread: 8 cells via 2x LDG.128.
// ---------------------------------------------------------------------------
__global__ __launch_bounds__(256) void k_pack_ini(const float* __restrict__ ini) {
    int tid  = threadIdx.x;
    int lane = tid & 31;
    int wrp  = tid >> 5;
    int b2   = blockIdx.x;
    const float4* p = (const float4*)(ini + (size_t)b2 * 2048);
    float4 f1 = p[tid * 2];
    float4 f2 = p[tid * 2 + 1];
    unsigned byte =
          (f1.x > 0.5f ? 1u : 0u)  | (f1.y > 0.5f ? 2u : 0u)
        | (f1.z > 0.5f ? 4u : 0u)  | (f1.w > 0.5f ? 8u : 0u)
        | (f2.x > 0.5f ? 16u : 0u) | (f2.y > 0.5f ? 32u : 0u)
        | (f2.z > 0.5f ? 64u : 0u) | (f2.w > 0.5f ? 128u : 0u);
    unsigned v = byte << ((lane & 3) * 8);
    v |= __shfl_xor_sync(0xffffffffu, v, 1);
    v |= __shfl_xor_sync(0xffffffffu, v, 2);
    if ((lane & 3) == 0)
        g_A[b2 * 64 + wrp * 8 + (lane >> 2)] = v;
}

// ---------------------------------------------------------------------------
// K2: blocks [0,512): 8-gen bit-sliced life; writes state FLOATS from smem
//     (vectorized) + g_B bits. Blocks [512,...): target copy (vectorized,
//     shifted STG.128) + pack g_T.
// ---------------------------------------------------------------------------
__device__ __forceinline__ void hsum(unsigned l, unsigned m, unsigned r,
                                     unsigned& h0, unsigned& h1) {
    unsigned L = __funnelshift_l(l, m, 1);
    unsigned R = __funnelshift_r(m, r, 1);
    unsigned t = L ^ R;
    h0 = t ^ m;
    h1 = (L & R) | (t & m);
}

__device__ __forceinline__ unsigned gol_combine(
    unsigned h0a, unsigned h1a, unsigned h0b, unsigned h1b,
    unsigned h0c, unsigned h1c, unsigned bm) {
    unsigned t  = h0a ^ h0b;
    unsigned s0 = t ^ h0c;
    unsigned c1 = (h0a & h0b) | (t & h0c);
    unsigned u  = h1a ^ h1b;
    unsigned p  = u ^ h1c;
    unsigned q  = (h1a & h1b) | (u & h1c);
    unsigned s1 = p ^ c1;
    unsigned c2 = p & c1;
    unsigned eq3 = s0 & s1 & ~(q | c2);
    unsigned eq4 = (q ^ c2) & ~(s0 | s1);
    return eq3 | (bm & eq4);
}

__device__ __forceinline__ float bit2f(unsigned w, int b) {
    return __uint_as_float(((w >> b) & 1u) * 0x3f800000u);
}

__global__ __launch_bounds__(256) void k_life_tgt(const float* __restrict__ tgt,
                                                  float* __restrict__ out) {
    int tid  = threadIdx.x;
    int lane = tid & 31;

    if (blockIdx.x >= NSIM) {
        // ================= target copy + pack role =================
        int t = (blockIdx.x - NSIM) * 256 + tid;   // handles cells [8t, 8t+8)
        const float4* t4 = (const float4*)tgt;
        float* outt = out + 1 + (size_t)NCELLS;

        float4 f1 = t4[2 * t];
        float4 f2 = t4[2 * t + 1];
        float4 f3 = make_float4(0.f, 0.f, 0.f, 0.f);
        if (2 * t + 2 < NCELLS / 4) f3 = t4[2 * t + 2];

        *(float4*)(outt + 8 * t + 3) = make_float4(f1.w, f2.x, f2.y, f2.z);
        if (8 * t + 7 != NCELLS - 1)
            *(float4*)(outt + 8 * t + 7) = make_float4(f2.w, f3.x, f3.y, f3.z);
        else
            outt[NCELLS - 1] = f2.w;
        if (t == 0) { outt[0] = f1.x; outt[1] = f1.y; outt[2] = f1.z; }

        unsigned byte =
              (f1.x > 0.5f ? 1u : 0u)  | (f1.y > 0.5f ? 2u : 0u)
            | (f1.z > 0.5f ? 4u : 0u)  | (f1.w > 0.5f ? 8u : 0u)
            | (f2.x > 0.5f ? 16u : 0u) | (f2.y > 0.5f ? 32u : 0u)
            | (f2.z > 0.5f ? 64u : 0u) | (f2.w > 0.5f ? 128u : 0u);
        unsigned v = byte << ((lane & 3) * 8);
        v |= __shfl_xor_sync(0xffffffffu, v, 1);
        v |= __shfl_xor_sync(0xffffffffu, v, 2);
        if ((lane & 3) == 0) g_T[t >> 2] = v;
        return;
    }

    // ================= life simulation role =================
    __shared__ unsigned sb[2][SH][SW];

    int tile = blockIdx.x;
    int b    = tile >> 4;
    int ty   = tile & 15;
    int r0   = ty * TH;

    const unsigned* img = g_A + b * WORDS_PER_IMG;

    for (int s = tid; s < SH; s += 256) {
        sb[0][s][0] = 0u; sb[0][s][33] = 0u;
        sb[1][s][0] = 0u; sb[1][s][33] = 0u;
    }
    for (int idx = tid; idx < SH * 32; idx += 256) {
        int s  = idx >> 5;
        int c  = idx & 31;
        int gr = r0 - 8 + s;
        unsigned v = ((unsigned)gr < (unsigned)HH) ? img[gr * WPR + c] : 0u;
        sb[0][s][c + 1] = v;
    }
    __syncthreads();

    int c      = tid & 31;
    int strip  = tid >> 5;
    int rstart = 1 + strip * 10;
    int rend   = (rstart + 10 < 79) ? (rstart + 10) : 79;

    #pragma unroll
    for (int g = 0; g < 8; ++g) {
        int cur = g & 1, nxt = cur ^ 1;

        unsigned h0a, h1a, h0b, h1b, h0c, h1c;
        hsum(sb[cur][rstart - 1][c], sb[cur][rstart - 1][c + 1], sb[cur][rstart - 1][c + 2], h0a, h1a);
        unsigned bm = sb[cur][rstart][c + 1];
        hsum(sb[cur][rstart][c], bm, sb[cur][rstart][c + 2], h0b, h1b);

        for (int r = rstart; r < rend; ++r) {
            unsigned nl = sb[cur][r + 1][c];
            unsigned nm = sb[cur][r + 1][c + 1];
            unsigned nr = sb[cur][r + 1][c + 2];
            hsum(nl, nm, nr, h0c, h1c);

            unsigned next = gol_combine(h0a, h1a, h0b, h1b, h0c, h1c, bm);
            if ((unsigned)(r0 - 8 + r) >= (unsigned)HH) next = 0u;
            sb[nxt][r][c + 1] = next;

            h0a = h0b; h1a = h1b;
            h0b = h0c; h1b = h1c;
            bm  = nm;
        }
        __syncthreads();
    }
    // final state in sb[0], interior smem rows [8,72) = tile-local words 0..2047

    // ---- write g_B bits (for K3 popc) ----
    unsigned* dst = g_B + b * WORDS_PER_IMG + r0 * WPR;
    for (int idx = tid; idx < TH * 32; idx += 256)
        dst[idx] = sb[0][8 + (idx >> 5)][(idx & 31) + 1];

    // ---- write state floats from smem: shifted quads + head/tail ----
    float* outs = out + 1 + ((size_t)b * HH + r0) * WW;  // tile cell base
    if (tid == 0) {
        unsigned w0 = sb[0][8][1];
        outs[0] = bit2f(w0, 0); outs[1] = bit2f(w0, 1); outs[2] = bit2f(w0, 2);
    }
    for (int k = tid; k < 16384; k += 256) {
        int bitpos = 3 + 4 * k;                        // tile-local cell index
        int w0i = bitpos >> 5;
        int sh  = bitpos & 31;
        unsigned lo = sb[0][8 + (w0i >> 5)][(w0i & 31) + 1];
        int w1i = w0i + 1;                             // ≤2048; row 72 exists (junk ok)
        unsigned hi = sb[0][8 + (w1i >> 5)][(w1i & 31) + 1];
        unsigned nib = __funnelshift_r(lo, hi, sh) & 0xFu;
        if (k < 16383) {
            float4 gq;
            gq.x = __uint_as_float((nib & 1u)        * 0x3f800000u);
            gq.y = __uint_as_float(((nib >> 1) & 1u) * 0x3f800000u);
            gq.z = __uint_as_float(((nib >> 2) & 1u) * 0x3f800000u);
            gq.w = __uint_as_float(((nib >> 3) & 1u) * 0x3f800000u);
            *(float4*)(outs + bitpos) = gq;
        } else {
            // tile tail: cell 65535 = bit 31 of last word
            outs[65535] = bit2f(sb[0][8 + 63][32], 31);
        }
    }
}

// ---------------------------------------------------------------------------
// K3: popc-only reduce over g_B / g_T (8 MB, L2-resident) + finalize.
// ---------------------------------------------------------------------------
__global__ __launch_bounds__(256) void k_reduce(float* __restrict__ out) {
    __shared__ int sh_live[8], sh_mism[8];
    int tid  = threadIdx.x;
    int lane = tid & 31;
    int wrp  = tid >> 5;
    int i = blockIdx.x * 256 + tid;                    // uint4 index
    const uint4* S = (const uint4*)g_B;
    const uint4* T = (const uint4*)g_T;
    uint4 s = S[i];
    uint4 t = T[i];
    int live = __popc(s.x) + __popc(s.y) + __popc(s.z) + __popc(s.w);
    int mism = __popc(s.x ^ t.x) + __popc(s.y ^ t.y)
             + __popc(s.z ^ t.z) + __popc(s.w ^ t.w);

    #pragma unroll
    for (int o = 16; o > 0; o >>= 1) {
        live += __shfl_down_sync(0xffffffffu, live, o);
        mism += __shfl_down_sync(0xffffffffu, mism, o);
    }
    if (lane == 0) { sh_live[wrp] = live; sh_mism[wrp] = mism; }
    __syncthreads();
    if (tid == 0) {
        int L = 0, M = 0;
        #pragma unroll
        for (int k = 0; k < 8; ++k) { L += sh_live[k]; M += sh_mism[k]; }
        atomicAdd(&g_live, (unsigned long long)L);
        atomicAdd(&g_mism, (unsigned long long)M);
        __threadfence();
        unsigned prev = atomicAdd(&g_done, 1u);
        if (prev == (unsigned)(NRED - 1)) {
            unsigned long long mt = atomicAdd(&g_mism, 0ull);
            unsigned long long lt = atomicAdd(&g_live, 0ull);
            out[0]              = (float)((double)mt / (double)NCELLS);  // loss
            out[1 + 2 * NCELLS] = (float)lt;                             // live_cells
            out[2 + 2 * NCELLS] = mt ? 1.0f : 0.0f;                      // max_abs_error
            g_live = 0ull; g_mism = 0ull;                                // replay reset
            __threadfence();
            g_done = 0u;
        }
    }
}

extern "C" void kernel_launch(void* const* d_in, const int* in_sizes, int n_in,
                              void* d_out, int out_size) {
    const float* initial = (const float*)d_in[0];
    const float* target  = (const float*)d_in[1];
    (void)in_sizes; (void)n_in; (void)out_size;   // generations fixed at 8

    float* out = (float*)d_out;

    k_pack_ini<<<NCELLS / 2048, 256>>>(initial);
    k_life_tgt<<<NSIM + NCOPY, 256>>>(target, out);
    k_reduce<<<NRED, 256>>>(out);
}